// round 3
// baseline (speedup 1.0000x reference)
#include <cuda_runtime.h>
#include <cuda_bf16.h>

// ---------------------------------------------------------------------------
// SelectiveSSM: y = scan(x, softplus(dt), B_in, C_in, A) + x*D
//   proj = x @ Wx^T (K-split x4 partials), dt fused into the scan kernel.
// ---------------------------------------------------------------------------

#define BATCH   4
#define SEQLEN  2048
#define DMODEL  1024
#define DSTATE  16
#define DTRANK  64
#define NPROJ   96
#define NROWS   (BATCH * SEQLEN)   // 8192
#define KSPLIT  4
#define KCHUNK  (DMODEL / KSPLIT)  // 256
#define CH      16                 // scan chunk (steps)
#define NCHUNK  (SEQLEN / CH)      // 128

// device scratch (allocation-free rule)
__device__ float g_projp[KSPLIT][NROWS * NPROJ];   // 4 x 3 MB partials

// ---------------------------------------------------------------------------
// Kernel 1: proj partial = x[:, kz*256:(kz+1)*256] @ Wx^T slice.
// Block tile 64(m) x 96(n), BK=32, 256 threads, 4x6 micro-tile. Grid 128x4.
// ---------------------------------------------------------------------------
__global__ __launch_bounds__(256, 4)
void proj_gemm_kernel(const float* __restrict__ x, const float* __restrict__ Wx)
{
    __shared__ float xs[32][65];   // [k][m]
    __shared__ float ws[32][97];   // [k][n]

    const int block_m = blockIdx.x * 64;
    const int kbase   = blockIdx.y * KCHUNK;
    const int t  = threadIdx.x;
    const int ty = t >> 4;        // 0..15
    const int tx = t & 15;        // 0..15

    float acc[4][6];
#pragma unroll
    for (int i = 0; i < 4; i++)
#pragma unroll
        for (int j = 0; j < 6; j++) acc[i][j] = 0.f;

    for (int k0 = kbase; k0 < kbase + KCHUNK; k0 += 32) {
#pragma unroll
        for (int i = t; i < 64 * 8; i += 256) {
            int m  = i >> 3;
            int kq = i & 7;
            float4 v = *(const float4*)&x[(size_t)(block_m + m) * DMODEL + k0 + kq * 4];
            xs[kq * 4 + 0][m] = v.x;
            xs[kq * 4 + 1][m] = v.y;
            xs[kq * 4 + 2][m] = v.z;
            xs[kq * 4 + 3][m] = v.w;
        }
#pragma unroll
        for (int i = t; i < 96 * 8; i += 256) {
            int n  = i >> 3;
            int kq = i & 7;
            float4 v = *(const float4*)&Wx[(size_t)n * DMODEL + k0 + kq * 4];
            ws[kq * 4 + 0][n] = v.x;
            ws[kq * 4 + 1][n] = v.y;
            ws[kq * 4 + 2][n] = v.z;
            ws[kq * 4 + 3][n] = v.w;
        }
        __syncthreads();

#pragma unroll
        for (int kk = 0; kk < 32; kk++) {
            float a[4], b[6];
#pragma unroll
            for (int i = 0; i < 4; i++) a[i] = xs[kk][ty * 4 + i];
#pragma unroll
            for (int j = 0; j < 6; j++) b[j] = ws[kk][tx * 6 + j];
#pragma unroll
            for (int i = 0; i < 4; i++)
#pragma unroll
                for (int j = 0; j < 6; j++) acc[i][j] = fmaf(a[i], b[j], acc[i][j]);
        }
        __syncthreads();
    }

    float* op = g_projp[blockIdx.y];
#pragma unroll
    for (int i = 0; i < 4; i++)
#pragma unroll
        for (int j = 0; j < 6; j++)
            op[(size_t)(block_m + ty * 4 + i) * NPROJ + tx * 6 + j] = acc[i][j];
}

// ---------------------------------------------------------------------------
// Kernel 2 (fused): dt-projection + softplus + selective scan.
// Block = 128 threads = 8 d-channels x 16 states; grid = (128, BATCH).
// ---------------------------------------------------------------------------
__device__ __forceinline__ float ex2f(float z)
{
    float r;
    asm("ex2.approx.ftz.f32 %0, %1;" : "=f"(r) : "f"(z));
    return r;
}
__device__ __forceinline__ float lg2f(float z)
{
    float r;
    asm("lg2.approx.ftz.f32 %0, %1;" : "=f"(r) : "f"(z));
    return r;
}
__device__ __forceinline__ float softplus_fast(float z)
{
    const float L2E = 1.4426950408889634f;
    const float LN2 = 0.6931471805599453f;
    float e = ex2f(-fabsf(z) * L2E);
    return fmaxf(z, 0.f) + lg2f(1.f + e) * LN2;
}

__global__ __launch_bounds__(128, 8)
void scan_fused_kernel(const float* __restrict__ x, const float* __restrict__ A_log,
                       const float* __restrict__ Dp, const float* __restrict__ dt_W,
                       const float* __restrict__ dt_b, float* __restrict__ out)
{
    __shared__ float projs[2][CH][100];   // staged proj rows (96 used, pad 100)
    __shared__ float xsh[2][CH][8];       // staged x values for the 8 channels
    __shared__ float wsm[8][64];          // dt_W rows for the 8 channels
    __shared__ float bias_s[8];

    const int b    = blockIdx.y;
    const int t    = threadIdx.x;
    const int s    = t & 15;
    const int dloc = t >> 4;
    const int d0   = blockIdx.x * 8;
    const int d    = d0 + dloc;

    // stage dt_W rows + bias (128 float4 exactly one per thread)
    {
        int row = t >> 4, k4 = t & 15;
        float4 v = *(const float4*)&dt_W[(size_t)(d0 + row) * DTRANK + k4 * 4];
        *(float4*)&wsm[row][k4 * 4] = v;
        if (t < 8) bias_s[t] = dt_b[d0 + t];
    }

    const float L2E = 1.4426950408889634f;
    const float A2  = -__expf(A_log[d * DSTATE + s]) * L2E;
    const float Dd  = Dp[d];

    const float* __restrict__ xb = x + (size_t)b * SEQLEN * DMODEL + d0;
    const size_t prow0 = (size_t)b * SEQLEN * NPROJ;
    float* __restrict__ ob = out + (size_t)b * SEQLEN * DMODEL;

    // staging registers: proj (3 float4/thread, summed over KSPLIT), x (1 float4 for t<32)
    float4 pr[3];
    float4 xr;

    auto load_chunk = [&](int c) {
        const size_t pbase = prow0 + (size_t)c * CH * NPROJ;   // float4-aligned (96*4B)
#pragma unroll
        for (int r = 0; r < 3; r++) {
            int idx = t + r * 128;                              // 0..383 float4
            float4 a = *(const float4*)&g_projp[0][pbase + idx * 4];
            float4 bb = *(const float4*)&g_projp[1][pbase + idx * 4];
            float4 cc = *(const float4*)&g_projp[2][pbase + idx * 4];
            float4 dd = *(const float4*)&g_projp[3][pbase + idx * 4];
            pr[r].x = a.x + bb.x + cc.x + dd.x;
            pr[r].y = a.y + bb.y + cc.y + dd.y;
            pr[r].z = a.z + bb.z + cc.z + dd.z;
            pr[r].w = a.w + bb.w + cc.w + dd.w;
        }
        if (t < 32) {
            int row = t >> 1, part = t & 1;
            xr = *(const float4*)&xb[(size_t)(c * CH + row) * DMODEL + part * 4];
        }
    };
    auto store_chunk = [&](int buf) {
#pragma unroll
        for (int r = 0; r < 3; r++) {
            int idx = t + r * 128;
            int row = idx / 24, c4 = idx % 24;                  // 24 float4 per 96-float row
            *(float4*)&projs[buf][row][c4 * 4] = pr[r];
        }
        if (t < 32) {
            int row = t >> 1, part = t & 1;
            *(float4*)&xsh[buf][row][part * 4] = xr;
        }
    };

    // prologue
    load_chunk(0);
    store_chunk(0);

    float h = 0.f;
    int p = 0;
    for (int c = 0; c < NCHUNK; c++) {
        __syncthreads();   // buf[p] visible; all reads of buf[p^1] (chunk c-1) done

        if (c + 1 < NCHUNK) load_chunk(c + 1);

        // per-thread dt for (l = c*CH + s, channel dloc)
        float acc = bias_s[dloc];
#pragma unroll
        for (int k4 = 0; k4 < 16; k4++) {
            float4 r4 = *(const float4*)&projs[p][s][k4 * 4];
            float4 w4 = *(const float4*)&wsm[dloc][k4 * 4];
            acc = fmaf(r4.x, w4.x, acc);
            acc = fmaf(r4.y, w4.y, acc);
            acc = fmaf(r4.z, w4.z, acc);
            acc = fmaf(r4.w, w4.w, acc);
        }
        float dtv = softplus_fast(acc);
        float dtx = dtv * xsh[p][s][dloc];

        // 16 scan steps
#pragma unroll
        for (int j = 0; j < 16; j++) {
            float dtv_j = __shfl_sync(0xffffffffu, dtv, j, 16);
            float dtx_j = __shfl_sync(0xffffffffu, dtx, j, 16);
            float Bs = projs[p][j][DTRANK + s];
            float Cs = projs[p][j][DTRANK + DSTATE + s];

            float dA = ex2f(dtv_j * A2);
            h = fmaf(h, dA, dtx_j * Bs);

            float pp = h * Cs;
            pp += __shfl_xor_sync(0xffffffffu, pp, 8);
            pp += __shfl_xor_sync(0xffffffffu, pp, 4);
            pp += __shfl_xor_sync(0xffffffffu, pp, 2);
            pp += __shfl_xor_sync(0xffffffffu, pp, 1);

            if (s == 0) {
                float xv = xsh[p][j][dloc];
                ob[(size_t)(c * CH + j) * DMODEL + d] = fmaf(xv, Dd, pp);
            }
        }

        if (c + 1 < NCHUNK) store_chunk(p ^ 1);
        p ^= 1;
    }
}

// ---------------------------------------------------------------------------
extern "C" void kernel_launch(void* const* d_in, const int* in_sizes, int n_in,
                              void* d_out, int out_size)
{
    const float* x     = (const float*)d_in[0];
    const float* A_log = (const float*)d_in[1];
    const float* D     = (const float*)d_in[2];
    const float* Wx    = (const float*)d_in[3];
    const float* dt_W  = (const float*)d_in[4];
    const float* dt_b  = (const float*)d_in[5];
    float* out = (float*)d_out;

    proj_gemm_kernel<<<dim3(NROWS / 64, KSPLIT), 256>>>(x, Wx);
    scan_fused_kernel<<<dim3(DMODEL / 8, BATCH), 128>>>(x, A_log, D, dt_W, dt_b, out);
}

// round 4
// speedup vs baseline: 1.6672x; 1.6672x over previous
#include <cuda_runtime.h>
#include <cuda_bf16.h>

// ---------------------------------------------------------------------------
// SelectiveSSM: y = scan(x, softplus(dt), B_in, C_in, A) + x*D
//   proj = x @ Wx^T (K-split x2 partials); dt-projection fused into scan.
// ---------------------------------------------------------------------------

#define BATCH   4
#define SEQLEN  2048
#define DMODEL  1024
#define DSTATE  16
#define DTRANK  64
#define NPROJ   96
#define NROWS   (BATCH * SEQLEN)   // 8192
#define KSPLIT  2
#define KCHUNK  (DMODEL / KSPLIT)  // 512
#define CH      16                 // scan chunk (steps)
#define NCHUNK  (SEQLEN / CH)      // 128
#define DBLK    16                 // d-channels per scan block

__device__ float g_projp[KSPLIT][NROWS * NPROJ];   // 2 x 3 MB partials

// ---------------------------------------------------------------------------
// Kernel 1: proj partial = x[:, kz*512:(kz+1)*512] @ Wx^T slice.
// Block tile 64(m) x 96(n), BK=32, 256 threads, 4x6 micro-tile. Grid 128x2.
// ---------------------------------------------------------------------------
__global__ __launch_bounds__(256, 4)
void proj_gemm_kernel(const float* __restrict__ x, const float* __restrict__ Wx)
{
    __shared__ float xs[32][65];
    __shared__ float ws[32][97];

    const int block_m = blockIdx.x * 64;
    const int kbase   = blockIdx.y * KCHUNK;
    const int t  = threadIdx.x;
    const int ty = t >> 4;
    const int tx = t & 15;

    float acc[4][6];
#pragma unroll
    for (int i = 0; i < 4; i++)
#pragma unroll
        for (int j = 0; j < 6; j++) acc[i][j] = 0.f;

    for (int k0 = kbase; k0 < kbase + KCHUNK; k0 += 32) {
#pragma unroll
        for (int i = t; i < 64 * 8; i += 256) {
            int m  = i >> 3;
            int kq = i & 7;
            float4 v = *(const float4*)&x[(size_t)(block_m + m) * DMODEL + k0 + kq * 4];
            xs[kq * 4 + 0][m] = v.x;
            xs[kq * 4 + 1][m] = v.y;
            xs[kq * 4 + 2][m] = v.z;
            xs[kq * 4 + 3][m] = v.w;
        }
#pragma unroll
        for (int i = t; i < 96 * 8; i += 256) {
            int n  = i >> 3;
            int kq = i & 7;
            float4 v = *(const float4*)&Wx[(size_t)n * DMODEL + k0 + kq * 4];
            ws[kq * 4 + 0][n] = v.x;
            ws[kq * 4 + 1][n] = v.y;
            ws[kq * 4 + 2][n] = v.z;
            ws[kq * 4 + 3][n] = v.w;
        }
        __syncthreads();

#pragma unroll
        for (int kk = 0; kk < 32; kk++) {
            float a[4], b[6];
#pragma unroll
            for (int i = 0; i < 4; i++) a[i] = xs[kk][ty * 4 + i];
#pragma unroll
            for (int j = 0; j < 6; j++) b[j] = ws[kk][tx * 6 + j];
#pragma unroll
            for (int i = 0; i < 4; i++)
#pragma unroll
                for (int j = 0; j < 6; j++) acc[i][j] = fmaf(a[i], b[j], acc[i][j]);
        }
        __syncthreads();
    }

    float* op = g_projp[blockIdx.y];
#pragma unroll
    for (int i = 0; i < 4; i++)
#pragma unroll
        for (int j = 0; j < 6; j++)
            op[(size_t)(block_m + ty * 4 + i) * NPROJ + tx * 6 + j] = acc[i][j];
}

// ---------------------------------------------------------------------------
// Kernel 2 (fused): dt-projection + softplus + selective scan.
// 128 threads = 16 channels x 8 q-lanes (2 states each). Grid (64, BATCH).
// Warp w owns channels 4w..4w+3; lane: dl = 4w + (lane&3), q = lane>>2,
// states {2q, 2q+1}. y-reduction: butterfly shfl over q (xor 4,8,16).
// ---------------------------------------------------------------------------
__device__ __forceinline__ float ex2f(float z)
{
    float r;
    asm("ex2.approx.ftz.f32 %0, %1;" : "=f"(r) : "f"(z));
    return r;
}
__device__ __forceinline__ float lg2f(float z)
{
    float r;
    asm("lg2.approx.ftz.f32 %0, %1;" : "=f"(r) : "f"(z));
    return r;
}
__device__ __forceinline__ float softplus_fast(float z)
{
    const float L2E = 1.4426950408889634f;
    const float LN2 = 0.6931471805599453f;
    float e = ex2f(-fabsf(z) * L2E);
    return fmaxf(z, 0.f) + lg2f(1.f + e) * LN2;
}

__global__ __launch_bounds__(128, 4)
void scan_fused_kernel(const float* __restrict__ x, const float* __restrict__ A_log,
                       const float* __restrict__ Dp, const float* __restrict__ dt_W,
                       const float* __restrict__ dt_b, float* __restrict__ out)
{
    __shared__ float prs[2][CH][100];    // staged proj rows (96 used)
    __shared__ float xsm[2][CH][DBLK];   // staged x
    __shared__ float dtsm[CH][17];       // per-chunk dt
    __shared__ float dtxsm[CH][17];      // per-chunk dt*x
    __shared__ float wsm[DBLK][68];      // dt_W rows (pad 68: conflict-free)
    __shared__ float bias_s[DBLK];

    const int b    = blockIdx.y;
    const int d0   = blockIdx.x * DBLK;
    const int t    = threadIdx.x;
    const int w    = t >> 5;
    const int lane = t & 31;
    const int dl   = (w << 2) + (lane & 3);  // channel 0..15
    const int s0   = (lane >> 2) * 2;        // first of 2 states

    // dot-phase mapping: thread handles row lq, channels dgrp & dgrp+8
    const int lq   = t & 15;
    const int dgrp = t >> 4;                 // 0..7

    // stage dt_W rows (256 float4) + bias
#pragma unroll
    for (int i = t; i < 256; i += 128) {
        int row = i >> 4, k4 = i & 15;
        float4 v = *(const float4*)&dt_W[(size_t)(d0 + row) * DTRANK + k4 * 4];
        *(float4*)&wsm[row][k4 * 4] = v;
    }
    if (t < DBLK) bias_s[t] = dt_b[d0 + t];

    const float L2E = 1.4426950408889634f;
    const float A2a = -__expf(A_log[(d0 + dl) * DSTATE + s0]) * L2E;
    const float A2b = -__expf(A_log[(d0 + dl) * DSTATE + s0 + 1]) * L2E;
    const float Dd  = Dp[d0 + dl];

    const float* __restrict__ xb = x + (size_t)b * SEQLEN * DMODEL + d0;
    const size_t prow0 = (size_t)b * SEQLEN * NPROJ;
    float* __restrict__ ob = out + (size_t)b * SEQLEN * DMODEL + d0;

    float4 pr[3];   // staged proj (summed partials)
    float4 xr;      // staged x (t < 64 only)

    auto load_chunk = [&](int c) {
        const size_t pbase = prow0 + (size_t)c * CH * NPROJ;
#pragma unroll
        for (int r = 0; r < 3; r++) {
            int idx = t + r * 128;   // float4 index 0..383
            float4 a  = *(const float4*)&g_projp[0][pbase + idx * 4];
            float4 bb = *(const float4*)&g_projp[1][pbase + idx * 4];
            pr[r].x = a.x + bb.x;
            pr[r].y = a.y + bb.y;
            pr[r].z = a.z + bb.z;
            pr[r].w = a.w + bb.w;
        }
        if (t < 64) {
            int row = t >> 2, c4 = t & 3;
            xr = *(const float4*)&xb[(size_t)(c * CH + row) * DMODEL + c4 * 4];
        }
    };
    auto store_chunk = [&](int buf) {
#pragma unroll
        for (int r = 0; r < 3; r++) {
            int idx = t + r * 128;
            int row = idx / 24, c4 = idx % 24;   // 24 float4 per 96-float row
            *(float4*)&prs[buf][row][c4 * 4] = pr[r];
        }
        if (t < 64) {
            int row = t >> 2, c4 = t & 3;
            *(float4*)&xsm[buf][row][c4 * 4] = xr;
        }
    };

    load_chunk(0);
    store_chunk(0);

    float h0 = 0.f, h1 = 0.f;
    int p = 0;
    for (int c = 0; c < NCHUNK; c++) {
        __syncthreads();   // buf p visible; dtsm free (prev scan reads done)

        if (c + 1 < NCHUNK) load_chunk(c + 1);

        // --- dt dot-products: 2 channels per thread, row lq ---
        {
            float acc0 = bias_s[dgrp];
            float acc1 = bias_s[dgrp + 8];
#pragma unroll
            for (int k4 = 0; k4 < 16; k4++) {
                float4 r4 = *(const float4*)&prs[p][lq][k4 * 4];
                float4 w0 = *(const float4*)&wsm[dgrp][k4 * 4];
                float4 w1 = *(const float4*)&wsm[dgrp + 8][k4 * 4];
                acc0 = fmaf(r4.x, w0.x, acc0);
                acc0 = fmaf(r4.y, w0.y, acc0);
                acc0 = fmaf(r4.z, w0.z, acc0);
                acc0 = fmaf(r4.w, w0.w, acc0);
                acc1 = fmaf(r4.x, w1.x, acc1);
                acc1 = fmaf(r4.y, w1.y, acc1);
                acc1 = fmaf(r4.z, w1.z, acc1);
                acc1 = fmaf(r4.w, w1.w, acc1);
            }
            float dt0 = softplus_fast(acc0);
            float dt1 = softplus_fast(acc1);
            dtsm[lq][dgrp]      = dt0;
            dtsm[lq][dgrp + 8]  = dt1;
            dtxsm[lq][dgrp]     = dt0 * xsm[p][lq][dgrp];
            dtxsm[lq][dgrp + 8] = dt1 * xsm[p][lq][dgrp + 8];
        }
        __syncthreads();   // dtsm/dtxsm visible

        if (c + 1 < NCHUNK) store_chunk(p ^ 1);   // buf p^1 free since chunk c-1

        // --- 16 scan steps ---
#pragma unroll
        for (int j = 0; j < CH; j++) {
            float dtv = dtsm[j][dl];
            float dtx = dtxsm[j][dl];
            float2 Bv = *(const float2*)&prs[p][j][DTRANK + s0];
            float2 Cv = *(const float2*)&prs[p][j][DTRANK + DSTATE + s0];

            float dA0 = ex2f(dtv * A2a);
            float dA1 = ex2f(dtv * A2b);
            h0 = fmaf(h0, dA0, dtx * Bv.x);
            h1 = fmaf(h1, dA1, dtx * Bv.y);

            float pp = fmaf(h1, Cv.y, h0 * Cv.x);
            pp += __shfl_xor_sync(0xffffffffu, pp, 4);
            pp += __shfl_xor_sync(0xffffffffu, pp, 8);
            pp += __shfl_xor_sync(0xffffffffu, pp, 16);

            if (lane < 4) {
                float xv = xsm[p][j][dl];
                ob[(size_t)(c * CH + j) * DMODEL + dl] = fmaf(xv, Dd, pp);
            }
        }

        p ^= 1;
    }
}

// ---------------------------------------------------------------------------
extern "C" void kernel_launch(void* const* d_in, const int* in_sizes, int n_in,
                              void* d_out, int out_size)
{
    const float* x     = (const float*)d_in[0];
    const float* A_log = (const float*)d_in[1];
    const float* D     = (const float*)d_in[2];
    const float* Wx    = (const float*)d_in[3];
    const float* dt_W  = (const float*)d_in[4];
    const float* dt_b  = (const float*)d_in[5];
    float* out = (float*)d_out;

    proj_gemm_kernel<<<dim3(NROWS / 64, KSPLIT), 256>>>(x, Wx);
    scan_fused_kernel<<<dim3(DMODEL / DBLK, BATCH), 128>>>(x, A_log, D, dt_W, dt_b, out);
}

// round 5
// speedup vs baseline: 1.8057x; 1.0831x over previous
#include <cuda_runtime.h>
#include <cuda_bf16.h>

// ---------------------------------------------------------------------------
// SelectiveSSM: y = scan(x, softplus(dt), B_in, C_in, A) + x*D
// ---------------------------------------------------------------------------

#define BATCH   4
#define SEQLEN  2048
#define DMODEL  1024
#define DSTATE  16
#define DTRANK  64
#define NPROJ   96
#define NROWS   (BATCH * SEQLEN)
#define KSPLIT  2
#define KCHUNK  (DMODEL / KSPLIT)
#define CH      16
#define NCHUNK  (SEQLEN / CH)      // 128
#define DBLK    16                 // channels per scan block
#define PP      100                // prs row pitch (floats)

__device__ float g_projp[KSPLIT][NROWS * NPROJ];

// ---------------------------------------------------------------------------
// f32x2 packed helpers (Blackwell)
// ---------------------------------------------------------------------------
typedef unsigned long long ull_t;
__device__ __forceinline__ ull_t pack2(float a, float b)
{ ull_t r; asm("mov.b64 %0,{%1,%2};" : "=l"(r) : "f"(a), "f"(b)); return r; }
__device__ __forceinline__ ull_t fma2(ull_t a, ull_t b, ull_t c)
{ ull_t d; asm("fma.rn.f32x2 %0,%1,%2,%3;" : "=l"(d) : "l"(a), "l"(b), "l"(c)); return d; }
__device__ __forceinline__ ull_t add2(ull_t a, ull_t b)
{ ull_t d; asm("add.rn.f32x2 %0,%1,%2;" : "=l"(d) : "l"(a), "l"(b)); return d; }
__device__ __forceinline__ float2 unpack2(ull_t a)
{ float2 f; asm("mov.b64 {%0,%1},%2;" : "=f"(f.x), "=f"(f.y) : "l"(a)); return f; }

__device__ __forceinline__ float ex2f(float z)
{ float r; asm("ex2.approx.ftz.f32 %0, %1;" : "=f"(r) : "f"(z)); return r; }
__device__ __forceinline__ float lg2f(float z)
{ float r; asm("lg2.approx.ftz.f32 %0, %1;" : "=f"(r) : "f"(z)); return r; }
__device__ __forceinline__ float softplus_fast(float z)
{
    const float L2E = 1.4426950408889634f;
    const float LN2 = 0.6931471805599453f;
    float e = ex2f(-fabsf(z) * L2E);
    return fmaxf(z, 0.f) + lg2f(1.f + e) * LN2;
}

// ---------------------------------------------------------------------------
// Kernel 1: proj partial = x[:, kz*512:(kz+1)*512] @ Wx^T slice. Grid 128x2.
// ---------------------------------------------------------------------------
__global__ __launch_bounds__(256, 4)
void proj_gemm_kernel(const float* __restrict__ x, const float* __restrict__ Wx)
{
    __shared__ float xs[32][65];
    __shared__ float ws[32][97];

    const int block_m = blockIdx.x * 64;
    const int kbase   = blockIdx.y * KCHUNK;
    const int t  = threadIdx.x;
    const int ty = t >> 4;
    const int tx = t & 15;

    float acc[4][6];
#pragma unroll
    for (int i = 0; i < 4; i++)
#pragma unroll
        for (int j = 0; j < 6; j++) acc[i][j] = 0.f;

    for (int k0 = kbase; k0 < kbase + KCHUNK; k0 += 32) {
#pragma unroll
        for (int i = t; i < 64 * 8; i += 256) {
            int m = i >> 3, kq = i & 7;
            float4 v = *(const float4*)&x[(size_t)(block_m + m) * DMODEL + k0 + kq * 4];
            xs[kq * 4 + 0][m] = v.x; xs[kq * 4 + 1][m] = v.y;
            xs[kq * 4 + 2][m] = v.z; xs[kq * 4 + 3][m] = v.w;
        }
#pragma unroll
        for (int i = t; i < 96 * 8; i += 256) {
            int n = i >> 3, kq = i & 7;
            float4 v = *(const float4*)&Wx[(size_t)n * DMODEL + k0 + kq * 4];
            ws[kq * 4 + 0][n] = v.x; ws[kq * 4 + 1][n] = v.y;
            ws[kq * 4 + 2][n] = v.z; ws[kq * 4 + 3][n] = v.w;
        }
        __syncthreads();

#pragma unroll
        for (int kk = 0; kk < 32; kk++) {
            float a[4], b[6];
#pragma unroll
            for (int i = 0; i < 4; i++) a[i] = xs[kk][ty * 4 + i];
#pragma unroll
            for (int j = 0; j < 6; j++) b[j] = ws[kk][tx * 6 + j];
#pragma unroll
            for (int i = 0; i < 4; i++)
#pragma unroll
                for (int j = 0; j < 6; j++) acc[i][j] = fmaf(a[i], b[j], acc[i][j]);
        }
        __syncthreads();
    }

    float* op = g_projp[blockIdx.y];
#pragma unroll
    for (int i = 0; i < 4; i++)
#pragma unroll
        for (int j = 0; j < 6; j++)
            op[(size_t)(block_m + ty * 4 + i) * NPROJ + tx * 6 + j] = acc[i][j];
}

// ---------------------------------------------------------------------------
// Kernel 2 (fused): dt-proj (f32x2) + softplus + scan, NS=4 states/thread.
// 64 threads = 2 warps; warp w owns channels 8w..8w+7.
// lane: dl = 8w + (lane&7), q = lane>>3, states 4q..4q+3.
// Reduction: 2 shfl (xor 8,16), deferred per 4-step sub-chunk.
// ---------------------------------------------------------------------------
__global__ __launch_bounds__(64, 8)
void scan_fused_kernel(const float* __restrict__ x, const float* __restrict__ A_log,
                       const float* __restrict__ Dp, const float* __restrict__ dt_W,
                       const float* __restrict__ dt_b, float* __restrict__ out)
{
    __shared__ float prs[2][CH][PP];
    __shared__ float xsm[2][CH][20];
    __shared__ float dtsm[CH][DBLK + 1];
    __shared__ float dtxsm[CH][DBLK + 1];
    __shared__ __align__(16) float2 wpA[4][64];   // (ch g, g+4) pairs
    __shared__ __align__(16) float2 wpB[4][64];   // (ch g+8, g+12) pairs
    __shared__ float bias_s[DBLK];

    const int b    = blockIdx.y;
    const int d0   = blockIdx.x * DBLK;
    const int t    = threadIdx.x;
    const int w    = t >> 5;
    const int lane = t & 31;
    const int dl   = (w << 3) + (lane & 7);
    const int q    = lane >> 3;          // 0..3
    const int s0   = q << 2;
    const int lq   = t & 15;             // dot-phase row
    const int dgrp = t >> 4;             // dot-phase channel group 0..3

    // stage dt_W as channel-pair float2s
    {
        int dg = t & 3, k0 = (t >> 2) * 4;
        float4 wa = *(const float4*)&dt_W[(size_t)(d0 + dg)      * DTRANK + k0];
        float4 wb = *(const float4*)&dt_W[(size_t)(d0 + dg + 4)  * DTRANK + k0];
        float4 wc = *(const float4*)&dt_W[(size_t)(d0 + dg + 8)  * DTRANK + k0];
        float4 wd = *(const float4*)&dt_W[(size_t)(d0 + dg + 12) * DTRANK + k0];
        wpA[dg][k0 + 0] = make_float2(wa.x, wb.x);
        wpA[dg][k0 + 1] = make_float2(wa.y, wb.y);
        wpA[dg][k0 + 2] = make_float2(wa.z, wb.z);
        wpA[dg][k0 + 3] = make_float2(wa.w, wb.w);
        wpB[dg][k0 + 0] = make_float2(wc.x, wd.x);
        wpB[dg][k0 + 1] = make_float2(wc.y, wd.y);
        wpB[dg][k0 + 2] = make_float2(wc.z, wd.z);
        wpB[dg][k0 + 3] = make_float2(wc.w, wd.w);
    }
    if (t < DBLK) bias_s[t] = dt_b[d0 + t];

    const float L2E = 1.4426950408889634f;
    float A2[4];
#pragma unroll
    for (int i = 0; i < 4; i++)
        A2[i] = -__expf(A_log[(size_t)(d0 + dl) * DSTATE + s0 + i]) * L2E;
    const float Dd = Dp[d0 + dl];

    const float* __restrict__ xb = x + (size_t)b * SEQLEN * DMODEL + d0;
    const size_t prow0 = (size_t)b * SEQLEN * NPROJ;
    float* __restrict__ ob = out + (size_t)b * SEQLEN * DMODEL + d0;

    float4 pr[6];
    float4 xr;

    auto load_chunk = [&](int c) {
        const size_t pbase = prow0 + (size_t)c * CH * NPROJ;
#pragma unroll
        for (int r = 0; r < 6; r++) {
            int idx = t + r * 64;
            float4 a  = *(const float4*)&g_projp[0][pbase + idx * 4];
            float4 b2 = *(const float4*)&g_projp[1][pbase + idx * 4];
            pr[r].x = a.x + b2.x; pr[r].y = a.y + b2.y;
            pr[r].z = a.z + b2.z; pr[r].w = a.w + b2.w;
        }
        xr = *(const float4*)&xb[(size_t)(c * CH + (t >> 2)) * DMODEL + (t & 3) * 4];
    };
    auto store_chunk = [&](int buf) {
#pragma unroll
        for (int r = 0; r < 6; r++) {
            int idx = t + r * 64;
            int row = idx / 24, c4 = idx % 24;
            *(float4*)&prs[buf][row][c4 * 4] = pr[r];
        }
        *(float4*)&xsm[buf][t >> 2][(t & 3) * 4] = xr;
    };

    load_chunk(0);
    store_chunk(0);
    load_chunk(1);

    float h0 = 0.f, h1 = 0.f, h2 = 0.f, h3 = 0.f;
    int p = 0;
    for (int c = 0; c < NCHUNK; c++) {
        __syncthreads();   // prs[p]/xsm[p] visible; dtsm free

        if (c + 1 < NCHUNK) store_chunk(p ^ 1);

        // --- dt dot: 4 channels per thread via packed f32x2, 4-way acc split ---
        {
            ull_t accA[4] = {0, 0, 0, 0}, accB[4] = {0, 0, 0, 0};
#pragma unroll
            for (int k4 = 0; k4 < 16; k4++) {
                float4 r4 = *(const float4*)&prs[p][lq][k4 * 4];
                ulonglong2 wa01 = *(const ulonglong2*)&wpA[dgrp][k4 * 4];
                ulonglong2 wa23 = *(const ulonglong2*)&wpA[dgrp][k4 * 4 + 2];
                ulonglong2 wb01 = *(const ulonglong2*)&wpB[dgrp][k4 * 4];
                ulonglong2 wb23 = *(const ulonglong2*)&wpB[dgrp][k4 * 4 + 2];
                int e = (k4 & 1) * 2;
                ull_t r0 = pack2(r4.x, r4.x);
                accA[e]     = fma2(r0, wa01.x, accA[e]);
                accB[e]     = fma2(r0, wb01.x, accB[e]);
                ull_t r1 = pack2(r4.y, r4.y);
                accA[e + 1] = fma2(r1, wa01.y, accA[e + 1]);
                accB[e + 1] = fma2(r1, wb01.y, accB[e + 1]);
                ull_t r2 = pack2(r4.z, r4.z);
                accA[e]     = fma2(r2, wa23.x, accA[e]);
                accB[e]     = fma2(r2, wb23.x, accB[e]);
                ull_t r3 = pack2(r4.w, r4.w);
                accA[e + 1] = fma2(r3, wa23.y, accA[e + 1]);
                accB[e + 1] = fma2(r3, wb23.y, accB[e + 1]);
            }
            float2 fA = unpack2(add2(add2(accA[0], accA[1]), add2(accA[2], accA[3])));
            float2 fB = unpack2(add2(add2(accB[0], accB[1]), add2(accB[2], accB[3])));
            float dt0 = softplus_fast(fA.x + bias_s[dgrp]);
            float dt1 = softplus_fast(fA.y + bias_s[dgrp + 4]);
            float dt2 = softplus_fast(fB.x + bias_s[dgrp + 8]);
            float dt3 = softplus_fast(fB.y + bias_s[dgrp + 12]);
            dtsm[lq][dgrp]      = dt0;
            dtsm[lq][dgrp + 4]  = dt1;
            dtsm[lq][dgrp + 8]  = dt2;
            dtsm[lq][dgrp + 12] = dt3;
            dtxsm[lq][dgrp]      = dt0 * xsm[p][lq][dgrp];
            dtxsm[lq][dgrp + 4]  = dt1 * xsm[p][lq][dgrp + 4];
            dtxsm[lq][dgrp + 8]  = dt2 * xsm[p][lq][dgrp + 8];
            dtxsm[lq][dgrp + 12] = dt3 * xsm[p][lq][dgrp + 12];
        }

        if (c + 2 < NCHUNK) load_chunk(c + 2);

        __syncthreads();   // dtsm/dtxsm + prs[p^1] visible

        // --- 16 scan steps, 4 sub-chunks with deferred reduction ---
#pragma unroll
        for (int sub = 0; sub < 4; sub++) {
            float pp[4];
#pragma unroll
            for (int jj = 0; jj < 4; jj++) {
                const int j = sub * 4 + jj;
                float dtv = dtsm[j][dl];
                float dtx = dtxsm[j][dl];
                float4 Bv = *(const float4*)&prs[p][j][DTRANK + s0];
                float4 Cv = *(const float4*)&prs[p][j][DTRANK + DSTATE + s0];

                float dA0 = ex2f(dtv * A2[0]);
                float dA1 = ex2f(dtv * A2[1]);
                float dA2 = ex2f(dtv * A2[2]);
                float dA3 = ex2f(dtv * A2[3]);
                h0 = fmaf(h0, dA0, dtx * Bv.x);
                h1 = fmaf(h1, dA1, dtx * Bv.y);
                h2 = fmaf(h2, dA2, dtx * Bv.z);
                h3 = fmaf(h3, dA3, dtx * Bv.w);

                pp[jj] = fmaf(h1, Cv.y, h0 * Cv.x) + fmaf(h3, Cv.w, h2 * Cv.z);
            }
            // independent reductions over q-lanes (bits 3,4)
#pragma unroll
            for (int jj = 0; jj < 4; jj++) {
                pp[jj] += __shfl_xor_sync(0xffffffffu, pp[jj], 8);
                pp[jj] += __shfl_xor_sync(0xffffffffu, pp[jj], 16);
            }
            // lane group q stores row sub*4+q
            float va = (q & 1) ? pp[1] : pp[0];
            float vb = (q & 1) ? pp[3] : pp[2];
            float v  = (q & 2) ? vb : va;
            int row = sub * 4 + q;
            float xv = xsm[p][row][dl];
            ob[(size_t)(c * CH + row) * DMODEL + dl] = fmaf(xv, Dd, v);
        }

        p ^= 1;
    }
}

// ---------------------------------------------------------------------------
extern "C" void kernel_launch(void* const* d_in, const int* in_sizes, int n_in,
                              void* d_out, int out_size)
{
    const float* x     = (const float*)d_in[0];
    const float* A_log = (const float*)d_in[1];
    const float* D     = (const float*)d_in[2];
    const float* Wx    = (const float*)d_in[3];
    const float* dt_W  = (const float*)d_in[4];
    const float* dt_b  = (const float*)d_in[5];
    float* out = (float*)d_out;

    proj_gemm_kernel<<<dim3(NROWS / 64, KSPLIT), 256>>>(x, Wx);
    scan_fused_kernel<<<dim3(DMODEL / DBLK, BATCH), 64>>>(x, A_log, D, dt_W, dt_b, out);
}

// round 6
// speedup vs baseline: 1.8547x; 1.0271x over previous
#include <cuda_runtime.h>
#include <cuda_bf16.h>

// ---------------------------------------------------------------------------
// SelectiveSSM: y = scan(x, softplus(dt), B_in, C_in, A) + x*D
// 3-phase parallel scan over S=8 sequence segments (linear recurrence):
//   passA: dt-proj + state-only scan from 0 per segment (+ decay product)
//   spine: combine segment states serially (exact, tiny)
//   passB: full scan per segment with correct h_init, y output
// ---------------------------------------------------------------------------

#define BATCH   4
#define SEQLEN  2048
#define DMODEL  1024
#define DSTATE  16
#define DTRANK  64
#define NPROJ   96
#define NROWS   (BATCH * SEQLEN)
#define KSPLIT  2
#define KCHUNK  (DMODEL / KSPLIT)
#define CH      16
#define DBLK    16
#define S       8
#define SEGLEN  (SEQLEN / S)       // 256
#define SEGCH   (SEGLEN / CH)      // 16
#define NSTATE  (BATCH * DMODEL * DSTATE)   // 65536

__device__ float g_projp[KSPLIT][NROWS * NPROJ];   // proj partials
__device__ float g_dt[NROWS * DMODEL];             // softplus(dt) from pass A
__device__ float g_hloc[S * NSTATE];
__device__ float g_dprod[S * NSTATE];
__device__ float g_hinit[S * NSTATE];

// ---------------------------------------------------------------------------
typedef unsigned long long ull_t;
__device__ __forceinline__ ull_t pack2(float a, float b)
{ ull_t r; asm("mov.b64 %0,{%1,%2};" : "=l"(r) : "f"(a), "f"(b)); return r; }
__device__ __forceinline__ ull_t fma2(ull_t a, ull_t b, ull_t c)
{ ull_t d; asm("fma.rn.f32x2 %0,%1,%2,%3;" : "=l"(d) : "l"(a), "l"(b), "l"(c)); return d; }
__device__ __forceinline__ ull_t add2(ull_t a, ull_t b)
{ ull_t d; asm("add.rn.f32x2 %0,%1,%2;" : "=l"(d) : "l"(a), "l"(b)); return d; }
__device__ __forceinline__ float2 unpack2(ull_t a)
{ float2 f; asm("mov.b64 {%0,%1},%2;" : "=f"(f.x), "=f"(f.y) : "l"(a)); return f; }
__device__ __forceinline__ float ex2f(float z)
{ float r; asm("ex2.approx.ftz.f32 %0, %1;" : "=f"(r) : "f"(z)); return r; }
__device__ __forceinline__ float lg2f(float z)
{ float r; asm("lg2.approx.ftz.f32 %0, %1;" : "=f"(r) : "f"(z)); return r; }
__device__ __forceinline__ float softplus_fast(float z)
{
    const float L2E = 1.4426950408889634f;
    const float LN2 = 0.6931471805599453f;
    float e = ex2f(-fabsf(z) * L2E);
    return fmaxf(z, 0.f) + lg2f(1.f + e) * LN2;
}

// ---------------------------------------------------------------------------
// Kernel 1: proj partial = x @ Wx^T K-slice. Grid 128x2.
// ---------------------------------------------------------------------------
__global__ __launch_bounds__(256, 4)
void proj_gemm_kernel(const float* __restrict__ x, const float* __restrict__ Wx)
{
    __shared__ float xs[32][65];
    __shared__ float ws[32][97];

    const int block_m = blockIdx.x * 64;
    const int kbase   = blockIdx.y * KCHUNK;
    const int t  = threadIdx.x;
    const int ty = t >> 4;
    const int tx = t & 15;

    float acc[4][6];
#pragma unroll
    for (int i = 0; i < 4; i++)
#pragma unroll
        for (int j = 0; j < 6; j++) acc[i][j] = 0.f;

    for (int k0 = kbase; k0 < kbase + KCHUNK; k0 += 32) {
#pragma unroll
        for (int i = t; i < 64 * 8; i += 256) {
            int m = i >> 3, kq = i & 7;
            float4 v = *(const float4*)&x[(size_t)(block_m + m) * DMODEL + k0 + kq * 4];
            xs[kq * 4 + 0][m] = v.x; xs[kq * 4 + 1][m] = v.y;
            xs[kq * 4 + 2][m] = v.z; xs[kq * 4 + 3][m] = v.w;
        }
#pragma unroll
        for (int i = t; i < 96 * 8; i += 256) {
            int n = i >> 3, kq = i & 7;
            float4 v = *(const float4*)&Wx[(size_t)n * DMODEL + k0 + kq * 4];
            ws[kq * 4 + 0][n] = v.x; ws[kq * 4 + 1][n] = v.y;
            ws[kq * 4 + 2][n] = v.z; ws[kq * 4 + 3][n] = v.w;
        }
        __syncthreads();

#pragma unroll
        for (int kk = 0; kk < 32; kk++) {
            float a[4], b[6];
#pragma unroll
            for (int i = 0; i < 4; i++) a[i] = xs[kk][ty * 4 + i];
#pragma unroll
            for (int j = 0; j < 6; j++) b[j] = ws[kk][tx * 6 + j];
#pragma unroll
            for (int i = 0; i < 4; i++)
#pragma unroll
                for (int j = 0; j < 6; j++) acc[i][j] = fmaf(a[i], b[j], acc[i][j]);
        }
        __syncthreads();
    }

    float* op = g_projp[blockIdx.y];
#pragma unroll
    for (int i = 0; i < 4; i++)
#pragma unroll
        for (int j = 0; j < 6; j++)
            op[(size_t)(block_m + ty * 4 + i) * NPROJ + tx * 6 + j] = acc[i][j];
}

// ---------------------------------------------------------------------------
// Pass A: dt-proj (f32x2) + state-only segment scan. Grid (64, BATCH, S).
// 64 threads; lane layout as R5 (dl = 8w+(lane&7), 4 states s0..s0+3).
// ---------------------------------------------------------------------------
__global__ __launch_bounds__(64, 8)
void scanA_kernel(const float* __restrict__ x, const float* __restrict__ A_log,
                  const float* __restrict__ dt_W, const float* __restrict__ dt_b)
{
    __shared__ float prs[2][CH][84];     // dt_r(64) + B(16) staged, pitch 84
    __shared__ float xsm[2][CH][20];
    __shared__ float dtsm[CH][DBLK + 1];
    __shared__ float dtxsm[CH][DBLK + 1];
    __shared__ __align__(16) float2 wpA[4][64];
    __shared__ __align__(16) float2 wpB[4][64];
    __shared__ float bias_s[DBLK];

    const int seg  = blockIdx.z;
    const int b    = blockIdx.y;
    const int d0   = blockIdx.x * DBLK;
    const int t    = threadIdx.x;
    const int w    = t >> 5;
    const int lane = t & 31;
    const int dl   = (w << 3) + (lane & 7);
    const int s0   = (lane >> 3) << 2;
    const int lq   = t & 15;
    const int dgrp = t >> 4;

    {
        int dg = t & 3, k0 = (t >> 2) * 4;
        float4 wa = *(const float4*)&dt_W[(size_t)(d0 + dg)      * DTRANK + k0];
        float4 wb = *(const float4*)&dt_W[(size_t)(d0 + dg + 4)  * DTRANK + k0];
        float4 wc = *(const float4*)&dt_W[(size_t)(d0 + dg + 8)  * DTRANK + k0];
        float4 wd = *(const float4*)&dt_W[(size_t)(d0 + dg + 12) * DTRANK + k0];
        wpA[dg][k0 + 0] = make_float2(wa.x, wb.x);
        wpA[dg][k0 + 1] = make_float2(wa.y, wb.y);
        wpA[dg][k0 + 2] = make_float2(wa.z, wb.z);
        wpA[dg][k0 + 3] = make_float2(wa.w, wb.w);
        wpB[dg][k0 + 0] = make_float2(wc.x, wd.x);
        wpB[dg][k0 + 1] = make_float2(wc.y, wd.y);
        wpB[dg][k0 + 2] = make_float2(wc.z, wd.z);
        wpB[dg][k0 + 3] = make_float2(wc.w, wd.w);
    }
    if (t < DBLK) bias_s[t] = dt_b[d0 + t];

    const float L2E = 1.4426950408889634f;
    float A2[4];
#pragma unroll
    for (int i = 0; i < 4; i++)
        A2[i] = -__expf(A_log[(size_t)(d0 + dl) * DSTATE + s0 + i]) * L2E;

    const int l0 = seg * SEGLEN;
    const float* __restrict__ xb = x + ((size_t)b * SEQLEN + l0) * DMODEL + d0;
    const size_t prow0 = (size_t)b * SEQLEN * NPROJ + (size_t)l0 * NPROJ;
    float* __restrict__ dtg = g_dt + ((size_t)b * SEQLEN + l0) * DMODEL + d0;

    float4 pr[5];
    float4 xr;

    auto load_chunk = [&](int c) {
        const size_t pbase = prow0 + (size_t)c * CH * NPROJ;
#pragma unroll
        for (int r = 0; r < 5; r++) {
            int idx = t + r * 64;        // 0..319 float4 over 80-float rows
            int row = idx / 20, c4 = idx % 20;
            size_t off = pbase + (size_t)row * NPROJ + c4 * 4;
            float4 a  = *(const float4*)&g_projp[0][off];
            float4 b2 = *(const float4*)&g_projp[1][off];
            pr[r].x = a.x + b2.x; pr[r].y = a.y + b2.y;
            pr[r].z = a.z + b2.z; pr[r].w = a.w + b2.w;
        }
        xr = *(const float4*)&xb[(size_t)(c * CH + (t >> 2)) * DMODEL + (t & 3) * 4];
    };
    auto store_chunk = [&](int buf) {
#pragma unroll
        for (int r = 0; r < 5; r++) {
            int idx = t + r * 64;
            int row = idx / 20, c4 = idx % 20;
            *(float4*)&prs[buf][row][c4 * 4] = pr[r];
        }
        *(float4*)&xsm[buf][t >> 2][(t & 3) * 4] = xr;
    };

    load_chunk(0);
    store_chunk(0);
    load_chunk(1);

    float h0 = 0.f, h1 = 0.f, h2 = 0.f, h3 = 0.f;
    float dp0 = 1.f, dp1 = 1.f, dp2 = 1.f, dp3 = 1.f;
    int p = 0;
    for (int c = 0; c < SEGCH; c++) {
        __syncthreads();

        if (c + 1 < SEGCH) store_chunk(p ^ 1);

        // dt dot: 4 channels/thread, packed f32x2
        {
            ull_t accA[4] = {0, 0, 0, 0}, accB[4] = {0, 0, 0, 0};
#pragma unroll
            for (int k4 = 0; k4 < 16; k4++) {
                float4 r4 = *(const float4*)&prs[p][lq][k4 * 4];
                ulonglong2 wa01 = *(const ulonglong2*)&wpA[dgrp][k4 * 4];
                ulonglong2 wa23 = *(const ulonglong2*)&wpA[dgrp][k4 * 4 + 2];
                ulonglong2 wb01 = *(const ulonglong2*)&wpB[dgrp][k4 * 4];
                ulonglong2 wb23 = *(const ulonglong2*)&wpB[dgrp][k4 * 4 + 2];
                int e = (k4 & 1) * 2;
                ull_t r0 = pack2(r4.x, r4.x);
                accA[e]     = fma2(r0, wa01.x, accA[e]);
                accB[e]     = fma2(r0, wb01.x, accB[e]);
                ull_t r1 = pack2(r4.y, r4.y);
                accA[e + 1] = fma2(r1, wa01.y, accA[e + 1]);
                accB[e + 1] = fma2(r1, wb01.y, accB[e + 1]);
                ull_t r2 = pack2(r4.z, r4.z);
                accA[e]     = fma2(r2, wa23.x, accA[e]);
                accB[e]     = fma2(r2, wb23.x, accB[e]);
                ull_t r3 = pack2(r4.w, r4.w);
                accA[e + 1] = fma2(r3, wa23.y, accA[e + 1]);
                accB[e + 1] = fma2(r3, wb23.y, accB[e + 1]);
            }
            float2 fA = unpack2(add2(add2(accA[0], accA[1]), add2(accA[2], accA[3])));
            float2 fB = unpack2(add2(add2(accB[0], accB[1]), add2(accB[2], accB[3])));
            float dt0 = softplus_fast(fA.x + bias_s[dgrp]);
            float dt1 = softplus_fast(fA.y + bias_s[dgrp + 4]);
            float dt2 = softplus_fast(fB.x + bias_s[dgrp + 8]);
            float dt3 = softplus_fast(fB.y + bias_s[dgrp + 12]);
            dtsm[lq][dgrp]      = dt0;
            dtsm[lq][dgrp + 4]  = dt1;
            dtsm[lq][dgrp + 8]  = dt2;
            dtsm[lq][dgrp + 12] = dt3;
            dtxsm[lq][dgrp]      = dt0 * xsm[p][lq][dgrp];
            dtxsm[lq][dgrp + 4]  = dt1 * xsm[p][lq][dgrp + 4];
            dtxsm[lq][dgrp + 8]  = dt2 * xsm[p][lq][dgrp + 8];
            dtxsm[lq][dgrp + 12] = dt3 * xsm[p][lq][dgrp + 12];
            // persist dt for pass B
            float* dr = dtg + (size_t)(c * CH + lq) * DMODEL;
            dr[dgrp]      = dt0;
            dr[dgrp + 4]  = dt1;
            dr[dgrp + 8]  = dt2;
            dr[dgrp + 12] = dt3;
        }

        if (c + 2 < SEGCH) load_chunk(c + 2);

        __syncthreads();

        // state-only scan: h update + decay product
#pragma unroll
        for (int j = 0; j < CH; j++) {
            float dtv = dtsm[j][dl];
            float dtx = dtxsm[j][dl];
            float4 Bv = *(const float4*)&prs[p][j][64 + s0];
            float dA0 = ex2f(dtv * A2[0]);
            float dA1 = ex2f(dtv * A2[1]);
            float dA2 = ex2f(dtv * A2[2]);
            float dA3 = ex2f(dtv * A2[3]);
            h0 = fmaf(h0, dA0, dtx * Bv.x);
            h1 = fmaf(h1, dA1, dtx * Bv.y);
            h2 = fmaf(h2, dA2, dtx * Bv.z);
            h3 = fmaf(h3, dA3, dtx * Bv.w);
            dp0 *= dA0; dp1 *= dA1; dp2 *= dA2; dp3 *= dA3;
        }

        p ^= 1;
    }

    const size_t hoff = (((size_t)seg * BATCH + b) * DMODEL + d0 + dl) * DSTATE + s0;
    *(float4*)&g_hloc[hoff]  = make_float4(h0, h1, h2, h3);
    *(float4*)&g_dprod[hoff] = make_float4(dp0, dp1, dp2, dp3);
}

// ---------------------------------------------------------------------------
// Spine: h_init[k] = h_loc[k-1] + dp[k-1] * h_init[k-1]  (exact, linear)
// ---------------------------------------------------------------------------
__global__ void spine_kernel()
{
    const int idx = blockIdx.x * 256 + threadIdx.x;   // 0..NSTATE-1
    float h = 0.f;
#pragma unroll
    for (int k = 0; k < S; k++) {
        g_hinit[(size_t)k * NSTATE + idx] = h;
        float hl = g_hloc[(size_t)k * NSTATE + idx];
        float dp = g_dprod[(size_t)k * NSTATE + idx];
        h = fmaf(dp, h, hl);
    }
}

// ---------------------------------------------------------------------------
// Pass B: full segment scan with h_init; dt precomputed. Grid (64, BATCH, S).
// ---------------------------------------------------------------------------
__global__ __launch_bounds__(64, 8)
void scanB_kernel(const float* __restrict__ x, const float* __restrict__ A_log,
                  const float* __restrict__ Dp, float* __restrict__ out)
{
    __shared__ float bcs[2][CH][36];    // B(16)+C(16) per row
    __shared__ float xsm[2][CH][20];
    __shared__ float dts[2][CH][20];

    const int seg  = blockIdx.z;
    const int b    = blockIdx.y;
    const int d0   = blockIdx.x * DBLK;
    const int t    = threadIdx.x;
    const int w    = t >> 5;
    const int lane = t & 31;
    const int dl   = (w << 3) + (lane & 7);
    const int q    = lane >> 3;
    const int s0   = q << 2;

    const float L2E = 1.4426950408889634f;
    float A2[4];
#pragma unroll
    for (int i = 0; i < 4; i++)
        A2[i] = -__expf(A_log[(size_t)(d0 + dl) * DSTATE + s0 + i]) * L2E;
    const float Dd = Dp[d0 + dl];

    const int l0 = seg * SEGLEN;
    const float* __restrict__ xb  = x    + ((size_t)b * SEQLEN + l0) * DMODEL + d0;
    const float* __restrict__ dtg = g_dt + ((size_t)b * SEQLEN + l0) * DMODEL + d0;
    const size_t prow0 = ((size_t)b * SEQLEN + l0) * NPROJ;
    float* __restrict__ ob = out + ((size_t)b * SEQLEN + l0) * DMODEL + d0;

    // initial state from spine
    float h0, h1, h2, h3;
    {
        const size_t hoff = (((size_t)seg * BATCH + b) * DMODEL + d0 + dl) * DSTATE + s0;
        float4 hv = *(const float4*)&g_hinit[hoff];
        h0 = hv.x; h1 = hv.y; h2 = hv.z; h3 = hv.w;
    }

    float4 bc[2], xr, dtr;

    auto load_chunk = [&](int c) {
        const size_t pbase = prow0 + (size_t)c * CH * NPROJ;
#pragma unroll
        for (int r = 0; r < 2; r++) {
            int idx = t + r * 64;            // 0..127: row=idx>>3, col8=idx&7
            size_t off = pbase + (size_t)(idx >> 3) * NPROJ + DTRANK + (idx & 7) * 4;
            float4 a  = *(const float4*)&g_projp[0][off];
            float4 b2 = *(const float4*)&g_projp[1][off];
            bc[r].x = a.x + b2.x; bc[r].y = a.y + b2.y;
            bc[r].z = a.z + b2.z; bc[r].w = a.w + b2.w;
        }
        int row = t >> 2, c4 = t & 3;
        xr  = *(const float4*)&xb [(size_t)(c * CH + row) * DMODEL + c4 * 4];
        dtr = *(const float4*)&dtg[(size_t)(c * CH + row) * DMODEL + c4 * 4];
    };
    auto store_chunk = [&](int buf) {
#pragma unroll
        for (int r = 0; r < 2; r++) {
            int idx = t + r * 64;
            *(float4*)&bcs[buf][idx >> 3][(idx & 7) * 4] = bc[r];
        }
        int row = t >> 2, c4 = t & 3;
        *(float4*)&xsm[buf][row][c4 * 4] = xr;
        *(float4*)&dts[buf][row][c4 * 4] = dtr;
    };

    load_chunk(0);
    store_chunk(0);
    load_chunk(1);

    int p = 0;
    for (int c = 0; c < SEGCH; c++) {
        __syncthreads();

        if (c + 1 < SEGCH) store_chunk(p ^ 1);
        if (c + 2 < SEGCH) load_chunk(c + 2);

#pragma unroll
        for (int sub = 0; sub < 4; sub++) {
            float pp[4];
#pragma unroll
            for (int jj = 0; jj < 4; jj++) {
                const int j = sub * 4 + jj;
                float dtv = dts[p][j][dl];
                float xvj = xsm[p][j][dl];
                float dtx = dtv * xvj;
                float4 Bv = *(const float4*)&bcs[p][j][s0];
                float4 Cv = *(const float4*)&bcs[p][j][16 + s0];

                float dA0 = ex2f(dtv * A2[0]);
                float dA1 = ex2f(dtv * A2[1]);
                float dA2 = ex2f(dtv * A2[2]);
                float dA3 = ex2f(dtv * A2[3]);
                h0 = fmaf(h0, dA0, dtx * Bv.x);
                h1 = fmaf(h1, dA1, dtx * Bv.y);
                h2 = fmaf(h2, dA2, dtx * Bv.z);
                h3 = fmaf(h3, dA3, dtx * Bv.w);

                pp[jj] = fmaf(h1, Cv.y, h0 * Cv.x) + fmaf(h3, Cv.w, h2 * Cv.z);
            }
#pragma unroll
            for (int jj = 0; jj < 4; jj++) {
                pp[jj] += __shfl_xor_sync(0xffffffffu, pp[jj], 8);
                pp[jj] += __shfl_xor_sync(0xffffffffu, pp[jj], 16);
            }
            float va = (q & 1) ? pp[1] : pp[0];
            float vb = (q & 1) ? pp[3] : pp[2];
            float v  = (q & 2) ? vb : va;
            int row = sub * 4 + q;
            float xv = xsm[p][row][dl];
            ob[(size_t)(c * CH + row) * DMODEL + dl] = fmaf(xv, Dd, v);
        }

        p ^= 1;
    }
}

// ---------------------------------------------------------------------------
extern "C" void kernel_launch(void* const* d_in, const int* in_sizes, int n_in,
                              void* d_out, int out_size)
{
    const float* x     = (const float*)d_in[0];
    const float* A_log = (const float*)d_in[1];
    const float* D     = (const float*)d_in[2];
    const float* Wx    = (const float*)d_in[3];
    const float* dt_W  = (const float*)d_in[4];
    const float* dt_b  = (const float*)d_in[5];
    float* out = (float*)d_out;

    proj_gemm_kernel<<<dim3(NROWS / 64, KSPLIT), 256>>>(x, Wx);
    scanA_kernel<<<dim3(DMODEL / DBLK, BATCH, S), 64>>>(x, A_log, dt_W, dt_b);
    spine_kernel<<<NSTATE / 256, 256>>>();
    scanB_kernel<<<dim3(DMODEL / DBLK, BATCH, S), 64>>>(x, A_log, D, out);
}